// round 12
// baseline (speedup 1.0000x reference)
#include <cuda_runtime.h>
#include <cuda_fp16.h>
#include <cstdint>
#include <cstddef>

#define BB 8
#define HH 128
#define WW 128
#define CC 64
#define FF 128
#define KT 9            // K*K taps
#define OC 18           // 2*KT offset channels
#define SC 576          // KT*CC sampled channels
#define KTOT (KT*SC)    // 5184 total GEMM K
#define NPIX (BB*HH*WW) // 131072

// Scratch (allocation-free rule: __device__ globals)
__device__ float  g_offsets[(size_t)NPIX * OC];  // ~9.4 MB
__device__ __half g_sh[(size_t)NPIX * SC];       // 151 MB (fp16 samples)
__device__ __half g_wh[(size_t)FF * KTOT];       // 1.33 MB [f][k] fp16

// ---------------------------------------------------------------------------
// helpers (all sm_80-era PTX — legal under compute_103)
// ---------------------------------------------------------------------------
__device__ __forceinline__ void cpa16(uint32_t dst, const void* src, int sz) {
    asm volatile("cp.async.cg.shared.global [%0], [%1], 16, %2;"
                 :: "r"(dst), "l"(src), "r"(sz));
}
__device__ __forceinline__ void cpa_commit() {
    asm volatile("cp.async.commit_group;" ::: "memory");
}
template <int N> __device__ __forceinline__ void cpa_wait() {
    asm volatile("cp.async.wait_group %0;" :: "n"(N) : "memory");
}
__device__ __forceinline__ void ldsm4(uint32_t* r, uint32_t addr) {
    asm volatile("ldmatrix.sync.aligned.m8n8.x4.shared.b16 {%0,%1,%2,%3}, [%4];"
                 : "=r"(r[0]), "=r"(r[1]), "=r"(r[2]), "=r"(r[3]) : "r"(addr));
}
__device__ __forceinline__ void mma16816(float* d, const uint32_t* a,
                                         uint32_t b0, uint32_t b1) {
    asm volatile(
        "mma.sync.aligned.m16n8k16.row.col.f32.f16.f16.f32 "
        "{%0,%1,%2,%3}, {%4,%5,%6,%7}, {%8,%9}, {%0,%1,%2,%3};"
        : "+f"(d[0]), "+f"(d[1]), "+f"(d[2]), "+f"(d[3])
        : "r"(a[0]), "r"(a[1]), "r"(a[2]), "r"(a[3]), "r"(b0), "r"(b1));
}
__device__ __forceinline__ uint32_t swz(uint32_t off) {
    return off ^ ((off >> 3) & 0x70u);
}

// ---------------------------------------------------------------------------
// Kernel 0: weight transpose + fp16 round.  Wt (3,3,576,128) -> g_wh[f][k]
// ---------------------------------------------------------------------------
__global__ __launch_bounds__(256) void wprep_kernel(const float* __restrict__ Wt)
{
    int idx = blockIdx.x * 256 + threadIdx.x;     // over FF*KTOT = 663552
    if (idx >= FF * KTOT) return;
    int kk = idx >> 7;
    int f  = idx & 127;
    g_wh[(size_t)f * KTOT + kk] = __float2half(Wt[idx]);
}

// ---------------------------------------------------------------------------
// Kernel 1: offset conv (3x3, C=64 -> 18), R7 version.
// ---------------------------------------------------------------------------
__global__ __launch_bounds__(256) void offset_conv_kernel(
    const float* __restrict__ x, const float* __restrict__ Woff,
    const float* __restrict__ boff)
{
    __shared__ float sWt[KT * OC * CC];     // [tap][o][c], 41.5KB
    __shared__ float sB[OC];
    int tid = threadIdx.x;
    for (int i = tid; i < KT * CC * OC; i += 256) {
        int tap = i / (CC * OC);
        int r   = i - tap * CC * OC;
        int c   = r / OC;
        int o   = r - c * OC;
        sWt[(tap * OC + o) * CC + c] = Woff[i];
    }
    if (tid < OC) sB[tid] = boff[tid];
    __syncthreads();

    int p0 = blockIdx.x * 512 + tid * 2;    // two adjacent pixels (same row)
    int b = p0 >> 14;
    int h = (p0 >> 7) & 127;
    int w = p0 & 127;

    float acc0[OC], acc1[OC];
#pragma unroll
    for (int o = 0; o < OC; o++) { acc0[o] = sB[o]; acc1[o] = sB[o]; }

    const float* xb = x + (size_t)(b * HH) * WW * CC;

    for (int ky = 0; ky < 3; ky++) {
        int y = h + ky - 1;
        bool yok = (unsigned)y < (unsigned)HH;
        for (int kx = 0; kx < 3; kx++) {
            int xx0 = w + kx - 1;
            int xx1 = xx0 + 1;
            bool ok0 = yok && (unsigned)xx0 < (unsigned)WW;
            bool ok1 = yok && (unsigned)xx1 < (unsigned)WW;
            if (!ok0 && !ok1) continue;
            const float* r0 = xb + ((size_t)y * WW + (ok0 ? xx0 : 0)) * CC;
            const float* r1 = xb + ((size_t)y * WW + (ok1 ? xx1 : 0)) * CC;
            const float* wt = sWt + (size_t)((ky * 3 + kx) * OC) * CC;
#pragma unroll 4
            for (int c4 = 0; c4 < CC; c4 += 4) {
                float4 a0 = ok0 ? *(const float4*)(r0 + c4)
                                : make_float4(0.f, 0.f, 0.f, 0.f);
                float4 a1 = ok1 ? *(const float4*)(r1 + c4)
                                : make_float4(0.f, 0.f, 0.f, 0.f);
#pragma unroll
                for (int o = 0; o < OC; o++) {
                    float4 w4 = *(const float4*)(wt + o * CC + c4);
                    acc0[o] += a0.x * w4.x + a0.y * w4.y + a0.z * w4.z + a0.w * w4.w;
                    acc1[o] += a1.x * w4.x + a1.y * w4.y + a1.z * w4.z + a1.w * w4.w;
                }
            }
        }
    }
    float* op0 = g_offsets + (size_t)p0 * OC;
#pragma unroll
    for (int o = 0; o < OC; o++) op0[o] = acc0[o];
#pragma unroll
    for (int o = 0; o < OC; o++) op0[OC + o] = acc1[o];
}

// ---------------------------------------------------------------------------
// Kernel 2: bilinear deformable sampling -> fp16 plane (R7 version).
// ---------------------------------------------------------------------------
__global__ __launch_bounds__(256) void sample_kernel(const float* __restrict__ x)
{
    int u = blockIdx.x * 16 + (threadIdx.x >> 4);   // (pixel,tap) unit
    int l16 = threadIdx.x & 15;
    int p = u / KT;
    int tap = u - p * KT;
    if (p >= NPIX) return;

    int b = p >> 14;
    int h = (p >> 7) & 127;
    int w = p & 127;

    float offx = __ldg(&g_offsets[(size_t)p * OC + tap * 2 + 0]);
    float offy = __ldg(&g_offsets[(size_t)p * OC + tap * 2 + 1]);

    float lx = (float)w + (float)(tap % 3) - 1.0f + offx;
    float ly = (float)h + (float)(tap / 3) - 1.0f + offy;
    lx = fminf(fmaxf(lx, 0.0f), (float)(WW - 1));
    ly = fminf(fmaxf(ly, 0.0f), (float)(HH - 1));

    float x0f = floorf(lx);
    float y0f = floorf(ly);
    float x1f = fminf(x0f + 1.0f, (float)(WW - 1));
    float y1f = fminf(y0f + 1.0f, (float)(HH - 1));

    float wa = (x1f - lx) * (y1f - ly);
    float wb = (x1f - lx) * (ly - y0f);
    float wc = (lx - x0f) * (y1f - ly);
    float wd = (lx - x0f) * (ly - y0f);

    int x0 = (int)x0f, x1 = (int)x1f, y0 = (int)y0f, y1 = (int)y1f;

    int c = l16 * 4;
    const float* xb = x + (size_t)b * HH * WW * CC + c;
    float4 Ia = *(const float4*)(xb + ((size_t)y0 * WW + x0) * CC);
    float4 Ib = *(const float4*)(xb + ((size_t)y1 * WW + x0) * CC);
    float4 Ic = *(const float4*)(xb + ((size_t)y0 * WW + x1) * CC);
    float4 Id = *(const float4*)(xb + ((size_t)y1 * WW + x1) * CC);

    float s0 = wa * Ia.x + wb * Ib.x + wc * Ic.x + wd * Id.x;
    float s1 = wa * Ia.y + wb * Ib.y + wc * Ic.y + wd * Id.y;
    float s2 = wa * Ia.z + wb * Ib.z + wc * Ic.z + wd * Id.z;
    float s3 = wa * Ia.w + wb * Ib.w + wc * Ic.w + wd * Id.w;

    __half2 h01 = __floats2half2_rn(s0, s1);
    __half2 h23 = __floats2half2_rn(s2, s3);
    uint2 pkt;
    pkt.x = *(uint32_t*)&h01;
    pkt.y = *(uint32_t*)&h23;
    *(uint2*)(g_sh + (size_t)p * SC + tap * CC + c) = pkt;
}

// ---------------------------------------------------------------------------
// Kernel 3: final conv GEMM, N-split tiles: M=128 x N=64, grid 2048.
// 128 threads / 4 warps (2Mx2N, 64x32 warp tiles = R7 inner loop).
// 3-stage pipeline, stage = A 16KB + B 8KB = 24KB -> 72KB smem -> 3 CTAs/SM.
// ---------------------------------------------------------------------------
#define ATILE 16384                  // A tile: 128 rows x 128B
#define BTILE 8192                   // B tile: 64 rows x 128B
#define STAGEB (ATILE + BTILE)       // 24KB
#define DSMEM  (3 * STAGEB + 1024)

__global__ __launch_bounds__(128, 3) void final_conv_mma(
    const float* __restrict__ bias, float* __restrict__ out)
{
    extern __shared__ char dsm[];
    __shared__ float sbias[FF];
    uint32_t tb = ((uint32_t)__cvta_generic_to_shared(dsm) + 1023) & ~1023u;
    int tid = threadIdx.x, wid = tid >> 5, l = tid & 31;
    int bx = blockIdx.x;
    int row = bx >> 1;               // 0..1023  (b*128 + h)
    int nh  = bx & 1;                // N half: cols nh*64 .. nh*64+63
    int b = row >> 7, h = row & 127;

    sbias[tid] = bias[tid];

    int q  = tid & 7;                // 16B unit within 128B row
    int rb = tid >> 3;               // row 0..15

    // constant swizzled smem dst offsets
    uint32_t dA[8], dB[4];
#pragma unroll
    for (int i = 0; i < 8; i++)
        dA[i] = swz((uint32_t)((i * 16 + rb) * 128 + q * 16));
#pragma unroll
    for (int i = 0; i < 4; i++)
        dB[i] = swz((uint32_t)((i * 16 + rb) * 128 + q * 16)) + ATILE;

    // B pointers: advance 128B/chunk (uniform); rows nh*64 .. nh*64+63
    const char* pb[4];
#pragma unroll
    for (int i = 0; i < 4; i++)
        pb[i] = (const char*)(g_wh + (size_t)(nh * 64 + i * 16 + rb) * KTOT + q * 8);
    // A pointers: recomputed at seg boundaries
    const char* pa[8];
    int szA[8];

    auto setupA = [&](int seg) {
        int ky = seg / 3, kx = seg - ky * 3;
        int y = h + ky - 1;
        bool yok = (unsigned)y < (unsigned)HH;
        size_t abase = (size_t)((b * HH + (yok ? y : 0)) * WW) * SC + q * 8;
#pragma unroll
        for (int i = 0; i < 8; i++) {
            int m = i * 16 + rb;
            int ws = m + kx - 1;
            bool ok = yok && ((unsigned)ws < (unsigned)WW);
            pa[i] = (const char*)(g_sh + abase + (size_t)(ok ? ws : 0) * SC);
            szA[i] = ok ? 16 : 0;
        }
    };
    auto load = [&](uint32_t base) {
#pragma unroll
        for (int i = 0; i < 8; i++) {
            cpa16(base + dA[i], pa[i], szA[i]);
            pa[i] += 128;
        }
#pragma unroll
        for (int i = 0; i < 4; i++) {
            cpa16(base + dB[i], pb[i], 16);
            pb[i] += 128;
        }
    };

    int mw = (wid & 1) * 64;     // warp M offset (0/64)
    int nw = (wid >> 1) * 32;    // warp N offset within tile (0/32)
    int lr = l & 15, lc = l >> 4;
    uint32_t aoff = swz((uint32_t)((mw + lr) * 128 + lc * 16));
    uint32_t boff = swz((uint32_t)((nw + lr) * 128 + lc * 16));

    float acc[4][4][4];
#pragma unroll
    for (int i = 0; i < 4; i++)
#pragma unroll
        for (int j = 0; j < 4; j++)
#pragma unroll
            for (int k = 0; k < 4; k++) acc[i][j][k] = 0.0f;

    setupA(0);
    load(tb + 0 * STAGEB); cpa_commit();
    load(tb + 1 * STAGEB); cpa_commit();

    int seg = 0, kin = 2;   // next prefetch chunk = seg*9 + kin

    for (int c = 0; c < 81; c++) {
        int s = c - (c / 3) * 3;
        if (c < 80) cpa_wait<1>(); else cpa_wait<0>();
        __syncthreads();

        if (c + 2 < 81) {
            if (kin == 9) { kin = 0; setupA(++seg); }
            int sp = (c + 2) - ((c + 2) / 3) * 3;
            load(tb + sp * STAGEB);
            cpa_commit();
            kin++;
        }

        uint32_t Ast = tb + s * STAGEB;
        uint32_t Bst = Ast + ATILE;

#pragma unroll
        for (int ks = 0; ks < 4; ks++) {          // 4 k-steps of k=16 fp16
            uint32_t dk = (uint32_t)(ks * 32);
            uint32_t ar[4][4], br[2][4];
#pragma unroll
            for (int mf = 0; mf < 4; mf++)
                ldsm4(ar[mf], Ast + mf * 2048 + (aoff ^ dk));
#pragma unroll
            for (int nb = 0; nb < 2; nb++)
                ldsm4(br[nb], Bst + nb * 2048 + (boff ^ dk));
#pragma unroll
            for (int mf = 0; mf < 4; mf++) {
#pragma unroll
                for (int nf = 0; nf < 4; nf++) {
                    int nb = nf >> 1, hi = nf & 1;
                    mma16816(acc[mf][nf], ar[mf], br[nb][hi], br[nb][hi + 2]);
                }
            }
        }
    }

    // epilogue: m = mw + mf*16 + l/4 (+8); n = nh*64 + nw + nf*8 + 2*(l%4)
#pragma unroll
    for (int mf = 0; mf < 4; mf++) {
#pragma unroll
        for (int nf = 0; nf < 4; nf++) {
            int m = mw + mf * 16 + (l >> 2);
            int n = nh * 64 + nw + nf * 8 + (l & 3) * 2;
            float bx0 = sbias[n], by0 = sbias[n + 1];
            float* o0 = out + ((size_t)row * 128 + m) * FF + n;
            float* o1 = o0 + 8 * FF;
            float2 v0 = make_float2(acc[mf][nf][0] + bx0, acc[mf][nf][1] + by0);
            float2 v1 = make_float2(acc[mf][nf][2] + bx0, acc[mf][nf][3] + by0);
            *(float2*)o0 = v0;
            *(float2*)o1 = v1;
        }
    }
}

// ---------------------------------------------------------------------------
extern "C" void kernel_launch(void* const* d_in, const int* in_sizes, int n_in,
                              void* d_out, int out_size)
{
    const float* x    = (const float*)d_in[0];  // (8,128,128,64)
    const float* Woff = (const float*)d_in[1];  // (3,3,64,18)
    const float* boff = (const float*)d_in[2];  // (18,)
    const float* Wt   = (const float*)d_in[3];  // (3,3,576,128)
    const float* bias = (const float*)d_in[4];  // (128,)
    float* out = (float*)d_out;                 // (8,128,128,128)

    cudaFuncSetAttribute(final_conv_mma,
                         cudaFuncAttributeMaxDynamicSharedMemorySize, DSMEM);

    wprep_kernel<<<(FF * KTOT + 255) / 256, 256>>>(Wt);
    offset_conv_kernel<<<NPIX / 512, 256>>>(x, Woff, boff);
    sample_kernel<<<(NPIX * KT + 15) / 16, 256>>>(x);
    final_conv_mma<<<BB * HH * 2, 128, DSMEM>>>(bias, out);
}

// round 14
// speedup vs baseline: 1.0748x; 1.0748x over previous
#include <cuda_runtime.h>
#include <cuda_fp16.h>
#include <cstdint>
#include <cstddef>

#define BB 8
#define HH 128
#define WW 128
#define CC 64
#define FF 128
#define KT 9            // K*K taps
#define OC 18           // 2*KT offset channels
#define SC 576          // KT*CC sampled channels
#define KTOT (KT*SC)    // 5184 total GEMM K
#define NPIX (BB*HH*WW) // 131072

// Scratch (allocation-free rule: __device__ globals)
__device__ __half g_sh[(size_t)NPIX * SC];       // 151 MB (fp16 samples)
__device__ __half g_wh[(size_t)FF * KTOT];       // 1.33 MB [f][k] fp16

// ---------------------------------------------------------------------------
// helpers (all sm_80-era PTX — legal under compute_103)
// ---------------------------------------------------------------------------
__device__ __forceinline__ void cpa16(uint32_t dst, const void* src, int sz) {
    asm volatile("cp.async.cg.shared.global [%0], [%1], 16, %2;"
                 :: "r"(dst), "l"(src), "r"(sz));
}
__device__ __forceinline__ void cpa_commit() {
    asm volatile("cp.async.commit_group;" ::: "memory");
}
template <int N> __device__ __forceinline__ void cpa_wait() {
    asm volatile("cp.async.wait_group %0;" :: "n"(N) : "memory");
}
__device__ __forceinline__ void ldsm4(uint32_t* r, uint32_t addr) {
    asm volatile("ldmatrix.sync.aligned.m8n8.x4.shared.b16 {%0,%1,%2,%3}, [%4];"
                 : "=r"(r[0]), "=r"(r[1]), "=r"(r[2]), "=r"(r[3]) : "r"(addr));
}
__device__ __forceinline__ void mma16816(float* d, const uint32_t* a,
                                         uint32_t b0, uint32_t b1) {
    asm volatile(
        "mma.sync.aligned.m16n8k16.row.col.f32.f16.f16.f32 "
        "{%0,%1,%2,%3}, {%4,%5,%6,%7}, {%8,%9}, {%0,%1,%2,%3};"
        : "+f"(d[0]), "+f"(d[1]), "+f"(d[2]), "+f"(d[3])
        : "r"(a[0]), "r"(a[1]), "r"(a[2]), "r"(a[3]), "r"(b0), "r"(b1));
}
__device__ __forceinline__ uint32_t swz(uint32_t off) {
    return off ^ ((off >> 3) & 0x70u);
}

// ---------------------------------------------------------------------------
// Fused prep kernel: 256 blocks x 256 threads; block = 512 pixels (4 rows).
//   phase 0: wprep slice (strided over all blocks)
//   phase 1: offset conv (R7 code, 2 px/thread), offsets -> smem
//   phase 2: bilinear sampling (R7 code, 16-lane units), offsets from smem
// Dynamic smem: sWt 41472B | sB 72B | soff 512*18*4B = 36864B  => ~78.4KB
// ---------------------------------------------------------------------------
#define PBLK (NPIX / 512)            // 256 blocks
#define PSMEM ((KT*OC*CC + OC + 512*OC + 2) * 4)

__global__ __launch_bounds__(256) void prep_kernel(
    const float* __restrict__ x, const float* __restrict__ Woff,
    const float* __restrict__ boff, const float* __restrict__ Wt)
{
    extern __shared__ float psm[];
    float* sWt  = psm;                       // [tap][o][c]
    float* sB   = psm + KT * OC * CC;
    float* soff = sB + OC;                   // [pxlocal][18]

    int tid = threadIdx.x;

    // ---- phase 0: weight convert slice: Wt (3,3,576,128) -> g_wh[f][k]
    for (int idx = blockIdx.x * 256 + tid; idx < FF * KTOT; idx += PBLK * 256) {
        int kk = idx >> 7;
        int f  = idx & 127;
        g_wh[(size_t)f * KTOT + kk] = __float2half(Wt[idx]);
    }

    // ---- load + transpose offset weights into smem
    for (int i = tid; i < KT * CC * OC; i += 256) {
        int tap = i / (CC * OC);
        int r   = i - tap * CC * OC;
        int c   = r / OC;
        int o   = r - c * OC;
        sWt[(tap * OC + o) * CC + c] = Woff[i];
    }
    if (tid < OC) sB[tid] = boff[tid];
    __syncthreads();

    // ---- phase 1: offset conv, 2 adjacent pixels per thread (R7)
    {
        int p0 = blockIdx.x * 512 + tid * 2;
        int b = p0 >> 14;
        int h = (p0 >> 7) & 127;
        int w = p0 & 127;

        float acc0[OC], acc1[OC];
#pragma unroll
        for (int o = 0; o < OC; o++) { acc0[o] = sB[o]; acc1[o] = sB[o]; }

        const float* xb = x + (size_t)(b * HH) * WW * CC;

        for (int ky = 0; ky < 3; ky++) {
            int y = h + ky - 1;
            bool yok = (unsigned)y < (unsigned)HH;
            for (int kx = 0; kx < 3; kx++) {
                int xx0 = w + kx - 1;
                int xx1 = xx0 + 1;
                bool ok0 = yok && (unsigned)xx0 < (unsigned)WW;
                bool ok1 = yok && (unsigned)xx1 < (unsigned)WW;
                if (!ok0 && !ok1) continue;
                const float* r0 = xb + ((size_t)y * WW + (ok0 ? xx0 : 0)) * CC;
                const float* r1 = xb + ((size_t)y * WW + (ok1 ? xx1 : 0)) * CC;
                const float* wt = sWt + (size_t)((ky * 3 + kx) * OC) * CC;
#pragma unroll 4
                for (int c4 = 0; c4 < CC; c4 += 4) {
                    float4 a0 = ok0 ? *(const float4*)(r0 + c4)
                                    : make_float4(0.f, 0.f, 0.f, 0.f);
                    float4 a1 = ok1 ? *(const float4*)(r1 + c4)
                                    : make_float4(0.f, 0.f, 0.f, 0.f);
#pragma unroll
                    for (int o = 0; o < OC; o++) {
                        float4 w4 = *(const float4*)(wt + o * CC + c4);
                        acc0[o] += a0.x * w4.x + a0.y * w4.y + a0.z * w4.z + a0.w * w4.w;
                        acc1[o] += a1.x * w4.x + a1.y * w4.y + a1.z * w4.z + a1.w * w4.w;
                    }
                }
            }
        }
        float* so = soff + (size_t)(tid * 2) * OC;
#pragma unroll
        for (int o = 0; o < OC; o++) so[o] = acc0[o];
#pragma unroll
        for (int o = 0; o < OC; o++) so[OC + o] = acc1[o];
    }
    __syncthreads();

    // ---- phase 2: bilinear sampling (16-lane units, float4 per lane)
    {
        int lu  = tid >> 4;        // unit 0..15
        int l16 = tid & 15;
        int c = l16 * 4;

        for (int pl = lu; pl < 512; pl += 16) {
            int p = blockIdx.x * 512 + pl;
            int b = p >> 14;
            int h = (p >> 7) & 127;
            int w = p & 127;
            const float* xb = x + (size_t)b * HH * WW * CC + c;
            __half* og = g_sh + (size_t)p * SC + c;
            const float* so = soff + (size_t)pl * OC;

#pragma unroll
            for (int tap = 0; tap < KT; tap++) {
                float offx = so[tap * 2 + 0];
                float offy = so[tap * 2 + 1];

                float lx = (float)w + (float)(tap % 3) - 1.0f + offx;
                float ly = (float)h + (float)(tap / 3) - 1.0f + offy;
                lx = fminf(fmaxf(lx, 0.0f), (float)(WW - 1));
                ly = fminf(fmaxf(ly, 0.0f), (float)(HH - 1));

                float x0f = floorf(lx);
                float y0f = floorf(ly);
                float x1f = fminf(x0f + 1.0f, (float)(WW - 1));
                float y1f = fminf(y0f + 1.0f, (float)(HH - 1));

                float wa = (x1f - lx) * (y1f - ly);
                float wb = (x1f - lx) * (ly - y0f);
                float wc = (lx - x0f) * (y1f - ly);
                float wd = (lx - x0f) * (ly - y0f);

                int x0 = (int)x0f, x1 = (int)x1f, y0 = (int)y0f, y1 = (int)y1f;

                float4 Ia = *(const float4*)(xb + ((size_t)y0 * WW + x0) * CC);
                float4 Ib = *(const float4*)(xb + ((size_t)y1 * WW + x0) * CC);
                float4 Ic = *(const float4*)(xb + ((size_t)y0 * WW + x1) * CC);
                float4 Id = *(const float4*)(xb + ((size_t)y1 * WW + x1) * CC);

                float s0 = wa * Ia.x + wb * Ib.x + wc * Ic.x + wd * Id.x;
                float s1 = wa * Ia.y + wb * Ib.y + wc * Ic.y + wd * Id.y;
                float s2 = wa * Ia.z + wb * Ib.z + wc * Ic.z + wd * Id.z;
                float s3 = wa * Ia.w + wb * Ib.w + wc * Ic.w + wd * Id.w;

                __half2 h01 = __floats2half2_rn(s0, s1);
                __half2 h23 = __floats2half2_rn(s2, s3);
                uint2 pkt;
                pkt.x = *(uint32_t*)&h01;
                pkt.y = *(uint32_t*)&h23;
                *(uint2*)(og + tap * CC) = pkt;
            }
        }
    }
}

// ---------------------------------------------------------------------------
// GEMM: R9 winner verbatim — 128 threads / 4 warps, 64x64 warp tiles,
// K=5184 in 81 chunks of 64, 3-stage cp.async, 2 CTAs/SM, incr. pointers.
// ---------------------------------------------------------------------------
#define TILEB 16384                  // one operand tile: 128 rows x 128B
#define STAGEB (2 * TILEB)           // A | B = 32KB
#define DSMEM  (3 * STAGEB + 1024)

__global__ __launch_bounds__(128, 2) void final_conv_mma(
    const float* __restrict__ bias, float* __restrict__ out)
{
    extern __shared__ char dsm[];
    __shared__ float sbias[FF];
    uint32_t tb = ((uint32_t)__cvta_generic_to_shared(dsm) + 1023) & ~1023u;
    int tid = threadIdx.x, wid = tid >> 5, l = tid & 31;
    int row = blockIdx.x, b = row >> 7, h = row & 127;

    sbias[tid] = bias[tid];

    int q  = tid & 7;                // 16B unit within 128B row
    int rb = tid >> 3;               // row 0..15

    uint32_t dA[8], dB[8];
#pragma unroll
    for (int i = 0; i < 8; i++) {
        int m = i * 16 + rb;
        dA[i] = swz((uint32_t)(m * 128 + q * 16));
        dB[i] = dA[i] + TILEB;
    }
    const char* pb[8];
#pragma unroll
    for (int i = 0; i < 8; i++)
        pb[i] = (const char*)(g_wh + (size_t)(i * 16 + rb) * KTOT + q * 8);
    const char* pa[8];
    int szA[8];

    auto setupA = [&](int seg) {
        int ky = seg / 3, kx = seg - ky * 3;
        int y = h + ky - 1;
        bool yok = (unsigned)y < (unsigned)HH;
        size_t abase = (size_t)((b * HH + (yok ? y : 0)) * WW) * SC + q * 8;
#pragma unroll
        for (int i = 0; i < 8; i++) {
            int m = i * 16 + rb;
            int ws = m + kx - 1;
            bool ok = yok && ((unsigned)ws < (unsigned)WW);
            pa[i] = (const char*)(g_sh + abase + (size_t)(ok ? ws : 0) * SC);
            szA[i] = ok ? 16 : 0;
        }
    };
    auto load = [&](uint32_t base) {
#pragma unroll
        for (int i = 0; i < 8; i++) {
            cpa16(base + dA[i], pa[i], szA[i]);
            pa[i] += 128;
        }
#pragma unroll
        for (int i = 0; i < 8; i++) {
            cpa16(base + dB[i], pb[i], 16);
            pb[i] += 128;
        }
    };

    int mw = (wid & 1) * 64;     // warp M offset (0/64)
    int nw = (wid >> 1) * 64;    // warp N offset (0/64)
    int lr = l & 15, lc = l >> 4;
    uint32_t aoff = swz((uint32_t)((mw + lr) * 128 + lc * 16));
    uint32_t boff = swz((uint32_t)((nw + lr) * 128 + lc * 16));

    float acc[4][8][4];
#pragma unroll
    for (int i = 0; i < 4; i++)
#pragma unroll
        for (int j = 0; j < 8; j++)
#pragma unroll
            for (int k = 0; k < 4; k++) acc[i][j][k] = 0.0f;

    setupA(0);
    load(tb + 0 * STAGEB); cpa_commit();
    load(tb + 1 * STAGEB); cpa_commit();

    int seg = 0, kin = 2;   // next prefetch chunk = seg*9 + kin

    for (int c = 0; c < 81; c++) {
        int s = c - (c / 3) * 3;
        if (c < 80) cpa_wait<1>(); else cpa_wait<0>();
        __syncthreads();

        if (c + 2 < 81) {
            if (kin == 9) { kin = 0; setupA(++seg); }
            int sp = (c + 2) - ((c + 2) / 3) * 3;
            load(tb + sp * STAGEB);
            cpa_commit();
            kin++;
        }

        uint32_t Ast = tb + s * STAGEB;
        uint32_t Bst = Ast + TILEB;

#pragma unroll
        for (int ks = 0; ks < 4; ks++) {          // 4 k-steps of k=16 fp16
            uint32_t dk = (uint32_t)(ks * 32);
            uint32_t ar[4][4], br[4][4];
#pragma unroll
            for (int mf = 0; mf < 4; mf++)
                ldsm4(ar[mf], Ast + mf * 2048 + (aoff ^ dk));
#pragma unroll
            for (int nb = 0; nb < 4; nb++)
                ldsm4(br[nb], Bst + nb * 2048 + (boff ^ dk));
#pragma unroll
            for (int mf = 0; mf < 4; mf++) {
#pragma unroll
                for (int nf = 0; nf < 8; nf++) {
                    int nb = nf >> 1, hi = nf & 1;
                    mma16816(acc[mf][nf], ar[mf], br[nb][hi], br[nb][hi + 2]);
                }
            }
        }
    }

#pragma unroll
    for (int mf = 0; mf < 4; mf++) {
#pragma unroll
        for (int nf = 0; nf < 8; nf++) {
            int m = mw + mf * 16 + (l >> 2);
            int n = nw + nf * 8 + (l & 3) * 2;
            float bx = sbias[n], by = sbias[n + 1];
            float* o0 = out + ((size_t)row * 128 + m) * FF + n;
            float* o1 = o0 + 8 * FF;
            float2 v0 = make_float2(acc[mf][nf][0] + bx, acc[mf][nf][1] + by);
            float2 v1 = make_float2(acc[mf][nf][2] + bx, acc[mf][nf][3] + by);
            *(float2*)o0 = v0;
            *(float2*)o1 = v1;
        }
    }
}

// ---------------------------------------------------------------------------
extern "C" void kernel_launch(void* const* d_in, const int* in_sizes, int n_in,
                              void* d_out, int out_size)
{
    const float* x    = (const float*)d_in[0];  // (8,128,128,64)
    const float* Woff = (const float*)d_in[1];  // (3,3,64,18)
    const float* boff = (const float*)d_in[2];  // (18,)
    const float* Wt   = (const float*)d_in[3];  // (3,3,576,128)
    const float* bias = (const float*)d_in[4];  // (128,)
    float* out = (float*)d_out;                 // (8,128,128,128)

    cudaFuncSetAttribute(prep_kernel,
                         cudaFuncAttributeMaxDynamicSharedMemorySize, PSMEM);
    cudaFuncSetAttribute(final_conv_mma,
                         cudaFuncAttributeMaxDynamicSharedMemorySize, DSMEM);

    prep_kernel<<<PBLK, 256, PSMEM>>>(x, Woff, boff, Wt);
    final_conv_mma<<<BB * HH, 128, DSMEM>>>(bias, out);
}

// round 15
// speedup vs baseline: 1.0787x; 1.0036x over previous
#include <cuda_runtime.h>
#include <cuda_fp16.h>
#include <cstdint>
#include <cstddef>

#define BB 8
#define HH 128
#define WW 128
#define CC 64
#define FF 128
#define KT 9            // K*K taps
#define OC 18           // 2*KT offset channels
#define SC 576          // KT*CC sampled channels
#define KTOT (KT*SC)    // 5184 total GEMM K
#define NPIX (BB*HH*WW) // 131072

// Scratch (allocation-free rule: __device__ globals)
__device__ __half g_sh[(size_t)NPIX * SC];       // 151 MB (fp16 samples)
__device__ __half g_wh[(size_t)FF * KTOT];       // 1.33 MB [f][k] fp16

// ---------------------------------------------------------------------------
// helpers (all sm_80-era PTX — legal under compute_103)
// ---------------------------------------------------------------------------
__device__ __forceinline__ void cpa16(uint32_t dst, const void* src, int sz) {
    asm volatile("cp.async.cg.shared.global [%0], [%1], 16, %2;"
                 :: "r"(dst), "l"(src), "r"(sz));
}
__device__ __forceinline__ void cpa_commit() {
    asm volatile("cp.async.commit_group;" ::: "memory");
}
template <int N> __device__ __forceinline__ void cpa_wait() {
    asm volatile("cp.async.wait_group %0;" :: "n"(N) : "memory");
}
__device__ __forceinline__ void ldsm4(uint32_t* r, uint32_t addr) {
    asm volatile("ldmatrix.sync.aligned.m8n8.x4.shared.b16 {%0,%1,%2,%3}, [%4];"
                 : "=r"(r[0]), "=r"(r[1]), "=r"(r[2]), "=r"(r[3]) : "r"(addr));
}
__device__ __forceinline__ void mma16816(float* d, const uint32_t* a,
                                         uint32_t b0, uint32_t b1) {
    asm volatile(
        "mma.sync.aligned.m16n8k16.row.col.f32.f16.f16.f32 "
        "{%0,%1,%2,%3}, {%4,%5,%6,%7}, {%8,%9}, {%0,%1,%2,%3};"
        : "+f"(d[0]), "+f"(d[1]), "+f"(d[2]), "+f"(d[3])
        : "r"(a[0]), "r"(a[1]), "r"(a[2]), "r"(a[3]), "r"(b0), "r"(b1));
}
__device__ __forceinline__ uint32_t swz(uint32_t off) {
    return off ^ ((off >> 3) & 0x70u);
}

// ---------------------------------------------------------------------------
// Fused prep kernel (R14 winner, unchanged): 256 blocks x 256 threads.
// ---------------------------------------------------------------------------
#define PBLK (NPIX / 512)            // 256 blocks
#define PSMEM ((KT*OC*CC + OC + 512*OC + 2) * 4)

__global__ __launch_bounds__(256) void prep_kernel(
    const float* __restrict__ x, const float* __restrict__ Woff,
    const float* __restrict__ boff, const float* __restrict__ Wt)
{
    extern __shared__ float psm[];
    float* sWt  = psm;                       // [tap][o][c]
    float* sB   = psm + KT * OC * CC;
    float* soff = sB + OC;                   // [pxlocal][18]

    int tid = threadIdx.x;

    for (int idx = blockIdx.x * 256 + tid; idx < FF * KTOT; idx += PBLK * 256) {
        int kk = idx >> 7;
        int f  = idx & 127;
        g_wh[(size_t)f * KTOT + kk] = __float2half(Wt[idx]);
    }

    for (int i = tid; i < KT * CC * OC; i += 256) {
        int tap = i / (CC * OC);
        int r   = i - tap * CC * OC;
        int c   = r / OC;
        int o   = r - c * OC;
        sWt[(tap * OC + o) * CC + c] = Woff[i];
    }
    if (tid < OC) sB[tid] = boff[tid];
    __syncthreads();

    {
        int p0 = blockIdx.x * 512 + tid * 2;
        int b = p0 >> 14;
        int h = (p0 >> 7) & 127;
        int w = p0 & 127;

        float acc0[OC], acc1[OC];
#pragma unroll
        for (int o = 0; o < OC; o++) { acc0[o] = sB[o]; acc1[o] = sB[o]; }

        const float* xb = x + (size_t)(b * HH) * WW * CC;

        for (int ky = 0; ky < 3; ky++) {
            int y = h + ky - 1;
            bool yok = (unsigned)y < (unsigned)HH;
            for (int kx = 0; kx < 3; kx++) {
                int xx0 = w + kx - 1;
                int xx1 = xx0 + 1;
                bool ok0 = yok && (unsigned)xx0 < (unsigned)WW;
                bool ok1 = yok && (unsigned)xx1 < (unsigned)WW;
                if (!ok0 && !ok1) continue;
                const float* r0 = xb + ((size_t)y * WW + (ok0 ? xx0 : 0)) * CC;
                const float* r1 = xb + ((size_t)y * WW + (ok1 ? xx1 : 0)) * CC;
                const float* wt = sWt + (size_t)((ky * 3 + kx) * OC) * CC;
#pragma unroll 4
                for (int c4 = 0; c4 < CC; c4 += 4) {
                    float4 a0 = ok0 ? *(const float4*)(r0 + c4)
                                    : make_float4(0.f, 0.f, 0.f, 0.f);
                    float4 a1 = ok1 ? *(const float4*)(r1 + c4)
                                    : make_float4(0.f, 0.f, 0.f, 0.f);
#pragma unroll
                    for (int o = 0; o < OC; o++) {
                        float4 w4 = *(const float4*)(wt + o * CC + c4);
                        acc0[o] += a0.x * w4.x + a0.y * w4.y + a0.z * w4.z + a0.w * w4.w;
                        acc1[o] += a1.x * w4.x + a1.y * w4.y + a1.z * w4.z + a1.w * w4.w;
                    }
                }
            }
        }
        float* so = soff + (size_t)(tid * 2) * OC;
#pragma unroll
        for (int o = 0; o < OC; o++) so[o] = acc0[o];
#pragma unroll
        for (int o = 0; o < OC; o++) so[OC + o] = acc1[o];
    }
    __syncthreads();

    {
        int lu  = tid >> 4;
        int l16 = tid & 15;
        int c = l16 * 4;

        for (int pl = lu; pl < 512; pl += 16) {
            int p = blockIdx.x * 512 + pl;
            int b = p >> 14;
            int h = (p >> 7) & 127;
            int w = p & 127;
            const float* xb = x + (size_t)b * HH * WW * CC + c;
            __half* og = g_sh + (size_t)p * SC + c;
            const float* so = soff + (size_t)pl * OC;

#pragma unroll
            for (int tap = 0; tap < KT; tap++) {
                float offx = so[tap * 2 + 0];
                float offy = so[tap * 2 + 1];

                float lx = (float)w + (float)(tap % 3) - 1.0f + offx;
                float ly = (float)h + (float)(tap / 3) - 1.0f + offy;
                lx = fminf(fmaxf(lx, 0.0f), (float)(WW - 1));
                ly = fminf(fmaxf(ly, 0.0f), (float)(HH - 1));

                float x0f = floorf(lx);
                float y0f = floorf(ly);
                float x1f = fminf(x0f + 1.0f, (float)(WW - 1));
                float y1f = fminf(y0f + 1.0f, (float)(HH - 1));

                float wa = (x1f - lx) * (y1f - ly);
                float wb = (x1f - lx) * (ly - y0f);
                float wc = (lx - x0f) * (y1f - ly);
                float wd = (lx - x0f) * (ly - y0f);

                int x0 = (int)x0f, x1 = (int)x1f, y0 = (int)y0f, y1 = (int)y1f;

                float4 Ia = *(const float4*)(xb + ((size_t)y0 * WW + x0) * CC);
                float4 Ib = *(const float4*)(xb + ((size_t)y1 * WW + x0) * CC);
                float4 Ic = *(const float4*)(xb + ((size_t)y0 * WW + x1) * CC);
                float4 Id = *(const float4*)(xb + ((size_t)y1 * WW + x1) * CC);

                float s0 = wa * Ia.x + wb * Ib.x + wc * Ic.x + wd * Id.x;
                float s1 = wa * Ia.y + wb * Ib.y + wc * Ic.y + wd * Id.y;
                float s2 = wa * Ia.z + wb * Ib.z + wc * Ic.z + wd * Id.z;
                float s3 = wa * Ia.w + wb * Ib.w + wc * Ic.w + wd * Id.w;

                __half2 h01 = __floats2half2_rn(s0, s1);
                __half2 h23 = __floats2half2_rn(s2, s3);
                uint2 pkt;
                pkt.x = *(uint32_t*)&h01;
                pkt.y = *(uint32_t*)&h23;
                *(uint2*)(og + tap * CC) = pkt;
            }
        }
    }
}

// ---------------------------------------------------------------------------
// GEMM with A-window reuse across kx.
// K reordered as (ky, cc, kx): j = ky*27 + cc*3 + kx, 81 iterations.
// A tile: 130 rows (w=-1..128, rows 0/129 permanently zero), loaded once per
// (ky,cc) superiter (every 3rd j), double-buffered. B: 16KB/iter, 3 stages.
// Same 4-warp 64x64 inner loop as R9; ldmatrix row base shifted by kx.
// ---------------------------------------------------------------------------
#define ATILE2 17408                 // 130 rows x 128B, padded to 17*1024
#define BTILE  16384
#define DSMEM  (2 * ATILE2 + 3 * BTILE + 1024)

__global__ __launch_bounds__(128, 2) void final_conv_mma(
    const float* __restrict__ bias, float* __restrict__ out)
{
    extern __shared__ char dsm[];
    __shared__ float sbias[FF];
    uint32_t tb = ((uint32_t)__cvta_generic_to_shared(dsm) + 1023) & ~1023u;
    uint32_t tbA = tb;
    uint32_t tbB = tb + 2 * ATILE2;
    int tid = threadIdx.x, wid = tid >> 5, l = tid & 31;
    int row = blockIdx.x, b = row >> 7, h = row & 127;

    sbias[tid] = bias[tid];

    int q  = tid & 7;                // 16B unit within 128B row
    int rb = tid >> 3;               // row 0..15

    // zero the permanent boundary rows (w=-1 -> row 0, w=128 -> row 129)
    if (tid < 32) {
        int buf = tid >> 4;          // 0/1
        int rr  = (tid >> 3) & 1;    // 0/1 -> row 0 / 129
        int u   = tid & 7;
        uint32_t addr = tbA + buf * ATILE2 + (rr ? 129 * 128 : 0) + u * 16;
        uint4 z = make_uint4(0, 0, 0, 0);
        *(uint4*)((char*)dsm + (addr - (uint32_t)__cvta_generic_to_shared(dsm))) = z;
    }

    // smem dst offsets
    uint32_t dAo[8], dBo[8];
#pragma unroll
    for (int i = 0; i < 8; i++) {
        dAo[i] = swz((uint32_t)((i * 16 + rb + 1) * 128 + q * 16));  // row = w+1
        dBo[i] = swz((uint32_t)((i * 16 + rb) * 128 + q * 16));
    }
    // B row base pointers (per thread, fixed)
    const char* pbb[8];
#pragma unroll
    for (int i = 0; i < 8; i++)
        pbb[i] = (const char*)(g_wh + (size_t)(i * 16 + rb) * KTOT + q * 8);
    // A pointers, recomputed per superiter
    const char* pa[8];
    int szA;

    auto setupA = [&](int s) {       // s = ky*9 + cc
        int ky = s / 9, cc = s - ky * 9;
        int y = h + ky - 1;
        bool yok = (unsigned)y < (unsigned)HH;
        size_t abase = ((size_t)(b * HH + (yok ? y : 0)) * WW) * SC + cc * 64 + q * 8;
        szA = yok ? 16 : 0;
#pragma unroll
        for (int i = 0; i < 8; i++)
            pa[i] = (const char*)(g_sh + abase + (size_t)(i * 16 + rb) * SC);
    };

    auto issue = [&](int j) {        // load group for iter j
        int jky = j / 27, rr = j - jky * 27;
        int jcc = rr / 3, jkx = rr - jcc * 3;
        uint32_t bidx = (uint32_t)(((jky * 3 + jkx) * 9 + jcc) * 128);
        uint32_t bs = tbB + (j % 3) * BTILE;
#pragma unroll
        for (int i = 0; i < 8; i++)
            cpa16(bs + dBo[i], pbb[i] + bidx, 16);
        if (jkx == 0) {
            int s = j / 3;
            setupA(s);
            uint32_t as = tbA + (s & 1) * ATILE2;
#pragma unroll
            for (int i = 0; i < 8; i++)
                cpa16(as + dAo[i], pa[i], szA);
        }
        cpa_commit();
    };

    int mw = (wid & 1) * 64;     // warp M offset (0/64)
    int nw = (wid >> 1) * 64;    // warp N offset (0/64)
    int lr = l & 15, lc = l >> 4;
    uint32_t aoffs[3];
#pragma unroll
    for (int kx = 0; kx < 3; kx++)
        aoffs[kx] = swz((uint32_t)((mw + lr + kx) * 128 + lc * 16));
    uint32_t boff = swz((uint32_t)((nw + lr) * 128 + lc * 16));

    float acc[4][8][4];
#pragma unroll
    for (int i = 0; i < 4; i++)
#pragma unroll
        for (int j = 0; j < 8; j++)
#pragma unroll
            for (int k = 0; k < 4; k++) acc[i][j][k] = 0.0f;

    issue(0);
    issue(1);

    for (int c = 0; c < 81; c++) {
        if (c < 80) cpa_wait<1>(); else cpa_wait<0>();
        __syncthreads();

        if (c + 2 < 81) issue(c + 2);

        int kx = c - (c / 3) * 3;
        int s  = c / 3;
        uint32_t Ast = tbA + (s & 1) * ATILE2;
        uint32_t Bst = tbB + kx * BTILE;     // j%3 == kx by construction
        uint32_t aoff = aoffs[kx];

#pragma unroll
        for (int ks = 0; ks < 4; ks++) {     // 4 k-steps of k=16 fp16
            uint32_t dk = (uint32_t)(ks * 32);
            uint32_t ar[4][4], br[4][4];
#pragma unroll
            for (int mf = 0; mf < 4; mf++)
                ldsm4(ar[mf], Ast + mf * 2048 + (aoff ^ dk));
#pragma unroll
            for (int nb = 0; nb < 4; nb++)
                ldsm4(br[nb], Bst + nb * 2048 + (boff ^ dk));
#pragma unroll
            for (int mf = 0; mf < 4; mf++) {
#pragma unroll
                for (int nf = 0; nf < 8; nf++) {
                    int nb = nf >> 1, hi = nf & 1;
                    mma16816(acc[mf][nf], ar[mf], br[nb][hi], br[nb][hi + 2]);
                }
            }
        }
    }

    // epilogue (R9): m = mw + mf*16 + l/4 (+8); n = nw + nf*8 + 2*(l%4)
#pragma unroll
    for (int mf = 0; mf < 4; mf++) {
#pragma unroll
        for (int nf = 0; nf < 8; nf++) {
            int m = mw + mf * 16 + (l >> 2);
            int n = nw + nf * 8 + (l & 3) * 2;
            float bx = sbias[n], by = sbias[n + 1];
            float* o0 = out + ((size_t)row * 128 + m) * FF + n;
            float* o1 = o0 + 8 * FF;
            float2 v0 = make_float2(acc[mf][nf][0] + bx, acc[mf][nf][1] + by);
            float2 v1 = make_float2(acc[mf][nf][2] + bx, acc[mf][nf][3] + by);
            *(float2*)o0 = v0;
            *(float2*)o1 = v1;
        }
    }
}

// ---------------------------------------------------------------------------
extern "C" void kernel_launch(void* const* d_in, const int* in_sizes, int n_in,
                              void* d_out, int out_size)
{
    const float* x    = (const float*)d_in[0];  // (8,128,128,64)
    const float* Woff = (const float*)d_in[1];  // (3,3,64,18)
    const float* boff = (const float*)d_in[2];  // (18,)
    const float* Wt   = (const float*)d_in[3];  // (3,3,576,128)
    const float* bias = (const float*)d_in[4];  // (128,)
    float* out = (float*)d_out;                 // (8,128,128,128)

    cudaFuncSetAttribute(prep_kernel,
                         cudaFuncAttributeMaxDynamicSharedMemorySize, PSMEM);
    cudaFuncSetAttribute(final_conv_mma,
                         cudaFuncAttributeMaxDynamicSharedMemorySize, DSMEM);

    prep_kernel<<<PBLK, 256, PSMEM>>>(x, Woff, boff, Wt);
    final_conv_mma<<<BB * HH, 128, DSMEM>>>(bias, out);
}